// round 4
// baseline (speedup 1.0000x reference)
#include <cuda_runtime.h>
#include <cstdint>

#define SRC_LEN 512
#define BATCH   64
#define HIDDEN  1024
#define EMBED   1024
#define NBLK    128          // scan CTAs = 32 j-tiles x 4 b-tiles

// Scratch (static __device__ arrays: allowed, no runtime allocation)
__device__ float    g_xproj[SRC_LEN * HIDDEN * BATCH];   // [t][j][b]
__device__ float    g_h[2][HIDDEN * BATCH];              // ping-pong, [k][b]
__device__ unsigned g_bar;

typedef unsigned long long ull;

__device__ __forceinline__ ull pk2(float x, float y) {
    ull r; asm("mov.b64 %0, {%1, %2};" : "=l"(r) : "f"(x), "f"(y)); return r;
}
__device__ __forceinline__ void upk2(ull p, float& x, float& y) {
    asm("mov.b64 {%0, %1}, %2;" : "=f"(x), "=f"(y) : "l"(p));
}
__device__ __forceinline__ ull ffma2(ull a, ull b, ull c) {
    ull d; asm("fma.rn.f32x2 %0, %1, %2, %3;" : "=l"(d) : "l"(a), "l"(b), "l"(c)); return d;
}

// ---------------------------------------------------------------------------
__global__ void init_kernel() {
    unsigned i = blockIdx.x * blockDim.x + threadIdx.x;
    if (i == 0) g_bar = 0u;
    if (i < HIDDEN * BATCH) g_h[0][i] = 0.0f;
}

// ncu-steering no-op: shifts launch alignment so `-s 5 -c 1` captures the scan.
__global__ void probe_kernel() { }

// ---------------------------------------------------------------------------
// Stage 1: x_proj[t][j][b] = sum_e emb[src[b,t]][e] * Wxh[j][e] + bxh[j]
// Tile 64(b) x 128(j) x 16(k). B quad reads split across warp-half parity so
// each LDS.128 covers 512B of 32 distinct addresses -> conflict-free.
// ---------------------------------------------------------------------------
__global__ __launch_bounds__(256) void xproj_kernel(
    const int*   __restrict__ src,
    const float* __restrict__ emb,
    const float* __restrict__ Wxh,
    const float* __restrict__ bxh)
{
    __shared__ __align__(16) float Ast[2][16][64];
    __shared__ __align__(16) float Bst[2][16][128];

    const int jt  = blockIdx.x;          // 0..7
    const int t   = blockIdx.y;          // 0..511
    const int tid = threadIdx.x;

    const int la_b = tid >> 2, la_e = tid & 3;    // A loader: 1 float4
    const int lb_j = tid >> 1, lb_e = tid & 1;    // B loader: 2 float4 (8 k)
    const int tx = tid & 15, ty = tid >> 4;       // micro-tile coords
    const int par = ty & 1;                       // warp-half parity

    const float* arow = emb + (size_t)__ldg(src + la_b * SRC_LEN + t) * EMBED;
    const float* brow = Wxh + (size_t)(jt * 128 + lb_j) * EMBED;

    ull acc[4][4];                                 // [4 b][2 quads x 2 f32x2]
#pragma unroll
    for (int i = 0; i < 4; ++i) { acc[i][0]=0; acc[i][1]=0; acc[i][2]=0; acc[i][3]=0; }

    float4 pa  = *(const float4*)(arow + la_e * 4);
    float4 pb0 = *(const float4*)(brow + lb_e * 8);
    float4 pb1 = *(const float4*)(brow + lb_e * 8 + 4);
    Ast[0][la_e*4+0][la_b]=pa.x;  Ast[0][la_e*4+1][la_b]=pa.y;
    Ast[0][la_e*4+2][la_b]=pa.z;  Ast[0][la_e*4+3][la_b]=pa.w;
    Bst[0][lb_e*8+0][lb_j]=pb0.x; Bst[0][lb_e*8+1][lb_j]=pb0.y;
    Bst[0][lb_e*8+2][lb_j]=pb0.z; Bst[0][lb_e*8+3][lb_j]=pb0.w;
    Bst[0][lb_e*8+4][lb_j]=pb1.x; Bst[0][lb_e*8+5][lb_j]=pb1.y;
    Bst[0][lb_e*8+6][lb_j]=pb1.z; Bst[0][lb_e*8+7][lb_j]=pb1.w;

    const int offA = par * 64 + tx * 4;            // this half's first quad
    const int offB = (par ^ 1) * 64 + tx * 4;      // the other quad

    const int NT = EMBED / 16;   // 64
    for (int i = 0; i < NT; ++i) {
        __syncthreads();
        const int cur = i & 1;
        if (i + 1 < NT) {
            const int e0 = (i + 1) * 16;
            pa  = *(const float4*)(arow + e0 + la_e * 4);
            pb0 = *(const float4*)(brow + e0 + lb_e * 8);
            pb1 = *(const float4*)(brow + e0 + lb_e * 8 + 4);
        }
#pragma unroll
        for (int kk = 0; kk < 16; ++kk) {
            float4     av = *(const float4*)    &Ast[cur][kk][ty * 4];
            ulonglong2 b0 = *(const ulonglong2*)&Bst[cur][kk][offA];
            ulonglong2 b1 = *(const ulonglong2*)&Bst[cur][kk][offB];
            ull p;
            p = pk2(av.x, av.x); acc[0][0]=ffma2(p,b0.x,acc[0][0]); acc[0][1]=ffma2(p,b0.y,acc[0][1]);
                                 acc[0][2]=ffma2(p,b1.x,acc[0][2]); acc[0][3]=ffma2(p,b1.y,acc[0][3]);
            p = pk2(av.y, av.y); acc[1][0]=ffma2(p,b0.x,acc[1][0]); acc[1][1]=ffma2(p,b0.y,acc[1][1]);
                                 acc[1][2]=ffma2(p,b1.x,acc[1][2]); acc[1][3]=ffma2(p,b1.y,acc[1][3]);
            p = pk2(av.z, av.z); acc[2][0]=ffma2(p,b0.x,acc[2][0]); acc[2][1]=ffma2(p,b0.y,acc[2][1]);
                                 acc[2][2]=ffma2(p,b1.x,acc[2][2]); acc[2][3]=ffma2(p,b1.y,acc[2][3]);
            p = pk2(av.w, av.w); acc[3][0]=ffma2(p,b0.x,acc[3][0]); acc[3][1]=ffma2(p,b0.y,acc[3][1]);
                                 acc[3][2]=ffma2(p,b1.x,acc[3][2]); acc[3][3]=ffma2(p,b1.y,acc[3][3]);
        }
        if (i + 1 < NT) {
            const int nxt = cur ^ 1;
            Ast[nxt][la_e*4+0][la_b]=pa.x;  Ast[nxt][la_e*4+1][la_b]=pa.y;
            Ast[nxt][la_e*4+2][la_b]=pa.z;  Ast[nxt][la_e*4+3][la_b]=pa.w;
            Bst[nxt][lb_e*8+0][lb_j]=pb0.x; Bst[nxt][lb_e*8+1][lb_j]=pb0.y;
            Bst[nxt][lb_e*8+2][lb_j]=pb0.z; Bst[nxt][lb_e*8+3][lb_j]=pb0.w;
            Bst[nxt][lb_e*8+4][lb_j]=pb1.x; Bst[nxt][lb_e*8+5][lb_j]=pb1.y;
            Bst[nxt][lb_e*8+6][lb_j]=pb1.z; Bst[nxt][lb_e*8+7][lb_j]=pb1.w;
        }
    }

    float c[4][8];
#pragma unroll
    for (int i = 0; i < 4; ++i) {
        upk2(acc[i][0], c[i][0], c[i][1]); upk2(acc[i][1], c[i][2], c[i][3]);
        upk2(acc[i][2], c[i][4], c[i][5]); upk2(acc[i][3], c[i][6], c[i][7]);
    }
    float* obase = g_xproj + (size_t)t * (HIDDEN * BATCH) + ty * 4;
#pragma unroll
    for (int g = 0; g < 2; ++g) {               // g=0 -> quad `par`, g=1 -> other
        const int quad = par ^ g;
#pragma unroll
        for (int jj = 0; jj < 4; ++jj) {
            const int j  = jt * 128 + quad * 64 + tx * 4 + jj;
            const float bj = __ldg(bxh + j);
            const int ci = g * 4 + jj;
            float4 v = make_float4(c[0][ci]+bj, c[1][ci]+bj, c[2][ci]+bj, c[3][ci]+bj);
            *(float4*)(obase + (size_t)j * BATCH) = v;
        }
    }
}

// ---------------------------------------------------------------------------
// Stage 2: persistent RNN scan, SMEM-staged h.
// 128 CTAs = 32 j-tiles x 4 b-tiles, 512 threads. CTA tile: 32 j x 16 b.
// SMEM: Wt[1024][32] (kg-swizzled j-quads, 128KB) + hst[1024][16]
// (kg-swizzled b-quads, 64KB; aliased by the reduction buffer).
// Thread (bg,jg,kg): 4b x 8j over a 32-k slice; acc packed along j.
// ---------------------------------------------------------------------------
__global__ __launch_bounds__(512, 1) void rnn_scan_kernel(
    const float* __restrict__ Whh, float* __restrict__ out)
{
    extern __shared__ __align__(16) float sm[];
    float* Wt  = sm;              // [1024][32]  131072 B
    float* hst = sm + 32768;      // [1024][16]  65536 B  (aliased: red[32][16][32])
    float* red = hst;

    const int tid = threadIdx.x;
    const int jt  = blockIdx.x >> 2;    // 0..31
    const int bt  = blockIdx.x & 3;     // 0..3

    // ---- load W rows jt*32..+31 transposed+swizzled, via 32x33 stage in red ----
    {
        const int kk = tid & 31, jh = tid >> 5;     // read coords (jh 0..15)
        const int j2 = tid & 31, kh = tid >> 5;     // write coords
        const int swj = ((j2 >> 3) * 8);            // base quad offset of j2
        const int j8  = j2 & 7;
        for (int k0 = 0; k0 < HIDDEN; k0 += 32) {
            red[jh * 33 + kk]        = __ldg(Whh + (size_t)(jt*32 + jh     ) * HIDDEN + k0 + kk);
            red[(jh + 16) * 33 + kk] = __ldg(Whh + (size_t)(jt*32 + jh + 16) * HIDDEN + k0 + kk);
            __syncthreads();
            const int kq = (k0 >> 5) & 3;           // (k>>5)&3, same for kh and kh+16
            const int col = (((j2 >> 3) + kq) & 3) * 8 + j8;
            Wt[(k0 + kh     ) * 32 + col] = red[j2 * 33 + kh];
            Wt[(k0 + kh + 16) * 32 + col] = red[j2 * 33 + kh + 16];
            __syncthreads();
        }
    }

    const int bg = tid & 3;             // 4 b-groups of 4
    const int jg = (tid >> 2) & 3;      // 4 j-groups of 8
    const int kg = tid >> 4;            // 0..31, k-slice of 32
    const int rb = tid & 15;            // reduction coords
    const int rj = tid >> 4;            // 0..31

    const float* hbase = hst + (kg * 32) * 16 + ((bg + kg) & 3) * 4;
    const float* wbase = Wt  + (kg * 32) * 32 + ((jg + kg) & 3) * 8;
    const float* xp    = g_xproj + (size_t)(jt * 32 + rj) * BATCH + bt * 16 + rb;
    const int    houto = (jt * 32 + rj) * BATCH + bt * 16 + rb;

    unsigned expected = 0;
    int   cur   = 0;
    float lastv = 0.0f;

    for (int t = 0; t < SRC_LEN; ++t) {
        const float xv = __ldcg(xp + (size_t)t * (HIDDEN * BATCH));

        // ---- stage h slice [1024 k][16 b] into SMEM (coalesced, kg-swizzle) ----
        const float* gh = g_h[cur] + bt * 16;
#pragma unroll
        for (int i = 0; i < 8; ++i) {
            const int idx = tid + i * 512;
            const int k = idx >> 2, bq = idx & 3;
            float4 v = __ldcg((const float4*)(gh + k * BATCH + bq * 4));
            *(float4*)&hst[k * 16 + ((bq + (k >> 5)) & 3) * 4] = v;
        }
        __syncthreads();

        // ---- accumulate: 32 k x (4b x 8j) ----
        ull a00=0,a01=0,a02=0,a03=0, a10=0,a11=0,a12=0,a13=0;
        ull a20=0,a21=0,a22=0,a23=0, a30=0,a31=0,a32=0,a33=0;
#pragma unroll
        for (int ki = 0; ki < 32; ++ki) {
            float4     h4 = *(const float4*)    (hbase + ki * 16);
            ulonglong2 wA = *(const ulonglong2*)(wbase + ki * 32);
            ulonglong2 wB = *(const ulonglong2*)(wbase + ki * 32 + 4);
            ull p;
            p = pk2(h4.x, h4.x); a00=ffma2(p,wA.x,a00); a01=ffma2(p,wA.y,a01);
                                 a02=ffma2(p,wB.x,a02); a03=ffma2(p,wB.y,a03);
            p = pk2(h4.y, h4.y); a10=ffma2(p,wA.x,a10); a11=ffma2(p,wA.y,a11);
                                 a12=ffma2(p,wB.x,a12); a13=ffma2(p,wB.y,a13);
            p = pk2(h4.z, h4.z); a20=ffma2(p,wA.x,a20); a21=ffma2(p,wA.y,a21);
                                 a22=ffma2(p,wB.x,a22); a23=ffma2(p,wB.y,a23);
            p = pk2(h4.w, h4.w); a30=ffma2(p,wA.x,a30); a31=ffma2(p,wA.y,a31);
                                 a32=ffma2(p,wB.x,a32); a33=ffma2(p,wB.y,a33);
        }
        __syncthreads();     // hst reads done before red (aliased) is written

        // ---- spill partials: red[kg][b][j] ----
        {
            float* rp = red + kg * 512 + (bg * 4) * 32 + jg * 8;
            *(ulonglong2*)(rp      ) = make_ulonglong2(a00, a01);
            *(ulonglong2*)(rp +   4) = make_ulonglong2(a02, a03);
            *(ulonglong2*)(rp +  32) = make_ulonglong2(a10, a11);
            *(ulonglong2*)(rp +  36) = make_ulonglong2(a12, a13);
            *(ulonglong2*)(rp +  64) = make_ulonglong2(a20, a21);
            *(ulonglong2*)(rp +  68) = make_ulonglong2(a22, a23);
            *(ulonglong2*)(rp +  96) = make_ulonglong2(a30, a31);
            *(ulonglong2*)(rp + 100) = make_ulonglong2(a32, a33);
        }
        __syncthreads();

        // ---- reduce 32 k-slices, tanh, store h (transposed [j][b]) ----
        float s = xv;
#pragma unroll
        for (int q = 0; q < 32; ++q) s += red[q * 512 + rb * 32 + rj];
        lastv = tanhf(s);
        __stcg(g_h[cur ^ 1] + houto, lastv);

        // ---- grid-wide barrier (monotonic counter, reset per launch) ----
        expected += NBLK;
        __threadfence();
        __syncthreads();
        if (tid == 0) {
            atomicAdd(&g_bar, 1u);
            while (*(volatile unsigned*)&g_bar < expected) { }
        }
        __syncthreads();
        cur ^= 1;
    }
    out[(size_t)(bt * 16 + rb) * HIDDEN + jt * 32 + rj] = lastv;
}

// ---------------------------------------------------------------------------
extern "C" void kernel_launch(void* const* d_in, const int* in_sizes, int n_in,
                              void* d_out, int out_size)
{
    const int*   src = (const int*)  d_in[0];
    const float* emb = (const float*)d_in[1];
    const float* Wxh = (const float*)d_in[2];
    const float* bxh = (const float*)d_in[3];
    const float* Whh = (const float*)d_in[4];
    float* out = (float*)d_out;

    static int smem_set = 0;
    const int scan_smem = (32768 + 16384) * sizeof(float);   // 196608 B
    if (!smem_set) {
        cudaFuncSetAttribute(rnn_scan_kernel,
                             cudaFuncAttributeMaxDynamicSharedMemorySize, scan_smem);
        smem_set = 1;
    }

    init_kernel<<<256, 256>>>();
    probe_kernel<<<1, 32>>>();       // ncu alignment: capture lands on the scan
    xproj_kernel<<<dim3(8, SRC_LEN), 256>>>(src, emb, Wxh, bxh);
    rnn_scan_kernel<<<NBLK, 512, scan_smem>>>(Whh, out);
}

// round 7
// speedup vs baseline: 1.4424x; 1.4424x over previous
#include <cuda_runtime.h>
#include <cstdint>

#define SRC_LEN 512
#define BATCH   64
#define HIDDEN  1024
#define EMBED   1024
#define NBLK    128          // scan CTAs = 32 j-tiles x 4 b-tiles

// Scratch (static __device__ arrays: allowed, no runtime allocation)
__device__ float    g_xproj[SRC_LEN * HIDDEN * BATCH];   // [t][j][b]
__device__ float    g_h[2][HIDDEN * BATCH];              // ping-pong, [k][b]
__device__ unsigned g_bar;

typedef unsigned long long ull;

__device__ __forceinline__ ull pk2(float x, float y) {
    ull r; asm("mov.b64 %0, {%1, %2};" : "=l"(r) : "f"(x), "f"(y)); return r;
}
__device__ __forceinline__ void upk2(ull p, float& x, float& y) {
    asm("mov.b64 {%0, %1}, %2;" : "=f"(x), "=f"(y) : "l"(p));
}
__device__ __forceinline__ ull ffma2(ull a, ull b, ull c) {
    ull d; asm("fma.rn.f32x2 %0, %1, %2, %3;" : "=l"(d) : "l"(a), "l"(b), "l"(c)); return d;
}

// ---------------------------------------------------------------------------
__global__ void init_kernel() {
    unsigned i = blockIdx.x * blockDim.x + threadIdx.x;
    if (i == 0) g_bar = 0u;
    if (i < HIDDEN * BATCH) g_h[0][i] = 0.0f;
}

// ncu-steering no-op: keeps launch alignment so `-s 5 -c 1` captures the scan.
__global__ void probe_kernel() { }

// ---------------------------------------------------------------------------
// Stage 1: x_proj[t][j][b] = sum_e emb[src[b,t]][e] * Wxh[j][e] + bxh[j]
// Tile 64(b) x 128(j) x 16(k); B quad reads split by warp-half parity.
// ---------------------------------------------------------------------------
__global__ __launch_bounds__(256) void xproj_kernel(
    const int*   __restrict__ src,
    const float* __restrict__ emb,
    const float* __restrict__ Wxh,
    const float* __restrict__ bxh)
{
    __shared__ __align__(16) float Ast[2][16][64];
    __shared__ __align__(16) float Bst[2][16][128];

    const int jt  = blockIdx.x;          // 0..7
    const int t   = blockIdx.y;          // 0..511
    const int tid = threadIdx.x;

    const int la_b = tid >> 2, la_e = tid & 3;
    const int lb_j = tid >> 1, lb_e = tid & 1;
    const int tx = tid & 15, ty = tid >> 4;
    const int par = ty & 1;

    const float* arow = emb + (size_t)__ldg(src + la_b * SRC_LEN + t) * EMBED;
    const float* brow = Wxh + (size_t)(jt * 128 + lb_j) * EMBED;

    ull acc[4][4];
#pragma unroll
    for (int i = 0; i < 4; ++i) { acc[i][0]=0; acc[i][1]=0; acc[i][2]=0; acc[i][3]=0; }

    float4 pa  = *(const float4*)(arow + la_e * 4);
    float4 pb0 = *(const float4*)(brow + lb_e * 8);
    float4 pb1 = *(const float4*)(brow + lb_e * 8 + 4);
    Ast[0][la_e*4+0][la_b]=pa.x;  Ast[0][la_e*4+1][la_b]=pa.y;
    Ast[0][la_e*4+2][la_b]=pa.z;  Ast[0][la_e*4+3][la_b]=pa.w;
    Bst[0][lb_e*8+0][lb_j]=pb0.x; Bst[0][lb_e*8+1][lb_j]=pb0.y;
    Bst[0][lb_e*8+2][lb_j]=pb0.z; Bst[0][lb_e*8+3][lb_j]=pb0.w;
    Bst[0][lb_e*8+4][lb_j]=pb1.x; Bst[0][lb_e*8+5][lb_j]=pb1.y;
    Bst[0][lb_e*8+6][lb_j]=pb1.z; Bst[0][lb_e*8+7][lb_j]=pb1.w;

    const int offA = par * 64 + tx * 4;
    const int offB = (par ^ 1) * 64 + tx * 4;

    const int NT = EMBED / 16;   // 64
    for (int i = 0; i < NT; ++i) {
        __syncthreads();
        const int cur = i & 1;
        if (i + 1 < NT) {
            const int e0 = (i + 1) * 16;
            pa  = *(const float4*)(arow + e0 + la_e * 4);
            pb0 = *(const float4*)(brow + e0 + lb_e * 8);
            pb1 = *(const float4*)(brow + e0 + lb_e * 8 + 4);
        }
#pragma unroll
        for (int kk = 0; kk < 16; ++kk) {
            float4     av = *(const float4*)    &Ast[cur][kk][ty * 4];
            ulonglong2 b0 = *(const ulonglong2*)&Bst[cur][kk][offA];
            ulonglong2 b1 = *(const ulonglong2*)&Bst[cur][kk][offB];
            ull p;
            p = pk2(av.x, av.x); acc[0][0]=ffma2(p,b0.x,acc[0][0]); acc[0][1]=ffma2(p,b0.y,acc[0][1]);
                                 acc[0][2]=ffma2(p,b1.x,acc[0][2]); acc[0][3]=ffma2(p,b1.y,acc[0][3]);
            p = pk2(av.y, av.y); acc[1][0]=ffma2(p,b0.x,acc[1][0]); acc[1][1]=ffma2(p,b0.y,acc[1][1]);
                                 acc[1][2]=ffma2(p,b1.x,acc[1][2]); acc[1][3]=ffma2(p,b1.y,acc[1][3]);
            p = pk2(av.z, av.z); acc[2][0]=ffma2(p,b0.x,acc[2][0]); acc[2][1]=ffma2(p,b0.y,acc[2][1]);
                                 acc[2][2]=ffma2(p,b1.x,acc[2][2]); acc[2][3]=ffma2(p,b1.y,acc[2][3]);
            p = pk2(av.w, av.w); acc[3][0]=ffma2(p,b0.x,acc[3][0]); acc[3][1]=ffma2(p,b0.y,acc[3][1]);
                                 acc[3][2]=ffma2(p,b1.x,acc[3][2]); acc[3][3]=ffma2(p,b1.y,acc[3][3]);
        }
        if (i + 1 < NT) {
            const int nxt = cur ^ 1;
            Ast[nxt][la_e*4+0][la_b]=pa.x;  Ast[nxt][la_e*4+1][la_b]=pa.y;
            Ast[nxt][la_e*4+2][la_b]=pa.z;  Ast[nxt][la_e*4+3][la_b]=pa.w;
            Bst[nxt][lb_e*8+0][lb_j]=pb0.x; Bst[nxt][lb_e*8+1][lb_j]=pb0.y;
            Bst[nxt][lb_e*8+2][lb_j]=pb0.z; Bst[nxt][lb_e*8+3][lb_j]=pb0.w;
            Bst[nxt][lb_e*8+4][lb_j]=pb1.x; Bst[nxt][lb_e*8+5][lb_j]=pb1.y;
            Bst[nxt][lb_e*8+6][lb_j]=pb1.z; Bst[nxt][lb_e*8+7][lb_j]=pb1.w;
        }
    }

    float c[4][8];
#pragma unroll
    for (int i = 0; i < 4; ++i) {
        upk2(acc[i][0], c[i][0], c[i][1]); upk2(acc[i][1], c[i][2], c[i][3]);
        upk2(acc[i][2], c[i][4], c[i][5]); upk2(acc[i][3], c[i][6], c[i][7]);
    }
    float* obase = g_xproj + (size_t)t * (HIDDEN * BATCH) + ty * 4;
#pragma unroll
    for (int g = 0; g < 2; ++g) {
        const int quad = par ^ g;
#pragma unroll
        for (int jj = 0; jj < 4; ++jj) {
            const int j  = jt * 128 + quad * 64 + tx * 4 + jj;
            const float bj = __ldg(bxh + j);
            const int ci = g * 4 + jj;
            float4 v = make_float4(c[0][ci]+bj, c[1][ci]+bj, c[2][ci]+bj, c[3][ci]+bj);
            *(float4*)(obase + (size_t)j * BATCH) = v;
        }
    }
}

// ---------------------------------------------------------------------------
// Stage 2: persistent RNN scan. 128 CTAs = 32 jt x 4 bt, 512 threads.
// warp = one 64-wide k-slice (16 warps); lane = (jg 0..7, bg 0..3) -> 4j x 4b.
// All lanes of a warp share k => every LDS is a small-set broadcast,
// conflict-free with NO swizzle. Spill stride 36 (2-way max), reduce 2-way.
// ---------------------------------------------------------------------------
__global__ __launch_bounds__(512, 1) void rnn_scan_kernel(
    const float* __restrict__ Whh, float* __restrict__ out)
{
    extern __shared__ __align__(16) float sm[];
    float* Wt  = sm;              // [1024][32]  131072 B, plain [k][j]
    float* hst = sm + 32768;      // [1024][16]  65536 B, plain [k][b]
    float* red = hst;             // aliased: [16 kg][16 b(x36)]

    const int tid = threadIdx.x;
    const int jt  = blockIdx.x >> 2;    // 0..31
    const int bt  = blockIdx.x & 3;     // 0..3

    // ---- load W rows jt*32..+31, transposed to [k][32j] via 32x33 stage ----
    {
        const int kk = tid & 31, jh = tid >> 5;     // read coords (jh 0..15)
        const int j2 = tid & 31, kh = tid >> 5;     // write coords
        for (int k0 = 0; k0 < HIDDEN; k0 += 32) {
            red[jh * 33 + kk]        = __ldg(Whh + (size_t)(jt*32 + jh     ) * HIDDEN + k0 + kk);
            red[(jh + 16) * 33 + kk] = __ldg(Whh + (size_t)(jt*32 + jh + 16) * HIDDEN + k0 + kk);
            __syncthreads();
            Wt[(k0 + kh     ) * 32 + j2] = red[j2 * 33 + kh];
            Wt[(k0 + kh + 16) * 32 + j2] = red[j2 * 33 + kh + 16];
            __syncthreads();
        }
    }

    const int kg = tid >> 5;            // warp id = k-slice (64 k)
    const int jg = tid & 7;             // j quad 0..7
    const int bg = (tid >> 3) & 3;      // b quad 0..3
    const int rb = tid & 15;            // reduce coords
    const int rj = tid >> 4;            // 0..31

    const float* wbase = Wt  + (kg * 64) * 32 + jg * 4;
    const float* hbase = hst + (kg * 64) * 16 + bg * 4;
    float*       rpill = red + kg * 576 + (bg * 4) * 36 + jg * 4;
    const float* xp    = g_xproj + (size_t)(jt * 32 + rj) * BATCH + bt * 16 + rb;
    const int    houto = (jt * 32 + rj) * BATCH + bt * 16 + rb;

    unsigned expected = 0;
    int   cur   = 0;
    float lastv = 0.0f;

    for (int t = 0; t < SRC_LEN; ++t) {
        const float xv = __ldcg(xp + (size_t)t * (HIDDEN * BATCH));

        // ---- stage h slice [1024 k][16 b] (coalesced LDG.128 -> STS.128) ----
        const float* gh = g_h[cur] + bt * 16;
#pragma unroll
        for (int i = 0; i < 8; ++i) {
            const int idx = tid + i * 512;
            const int k = idx >> 2, bq = idx & 3;
            float4 v = __ldcg((const float4*)(gh + k * BATCH + bq * 4));
            *(float4*)&hst[k * 16 + bq * 4] = v;
        }
        __syncthreads();

        // ---- accumulate: 64 k x (4b x 4j), 8 FFMA2 per k ----
        ull a00=0,a01=0, a10=0,a11=0, a20=0,a21=0, a30=0,a31=0;
#pragma unroll 8
        for (int k = 0; k < 64; ++k) {
            float4     h4 = *(const float4*)    (hbase + k * 16);
            ulonglong2 w2 = *(const ulonglong2*)(wbase + k * 32);
            ull p;
            p = pk2(h4.x, h4.x); a00=ffma2(p,w2.x,a00); a01=ffma2(p,w2.y,a01);
            p = pk2(h4.y, h4.y); a10=ffma2(p,w2.x,a10); a11=ffma2(p,w2.y,a11);
            p = pk2(h4.z, h4.z); a20=ffma2(p,w2.x,a20); a21=ffma2(p,w2.y,a21);
            p = pk2(h4.w, h4.w); a30=ffma2(p,w2.x,a30); a31=ffma2(p,w2.y,a31);
        }
        __syncthreads();     // hst reads done before red (aliased) is written

        // ---- spill partials: red[kg][b][j], stride 36 ----
        *(ulonglong2*)(rpill         ) = make_ulonglong2(a00, a01);
        *(ulonglong2*)(rpill + 1 * 36) = make_ulonglong2(a10, a11);
        *(ulonglong2*)(rpill + 2 * 36) = make_ulonglong2(a20, a21);
        *(ulonglong2*)(rpill + 3 * 36) = make_ulonglong2(a30, a31);
        __syncthreads();

        // ---- reduce 16 k-slices, tanh, store h ----
        float s = xv;
#pragma unroll
        for (int q = 0; q < 16; ++q) s += red[q * 576 + rb * 36 + rj];
        lastv = tanhf(s);
        __stcg(g_h[cur ^ 1] + houto, lastv);

        // ---- grid-wide barrier (monotonic counter, reset per launch) ----
        expected += NBLK;
        __threadfence();
        __syncthreads();
        if (tid == 0) {
            atomicAdd(&g_bar, 1u);
            while (*(volatile unsigned*)&g_bar < expected) { }
        }
        __syncthreads();
        cur ^= 1;
    }
    out[(size_t)(bt * 16 + rb) * HIDDEN + jt * 32 + rj] = lastv;
}

// ---------------------------------------------------------------------------
extern "C" void kernel_launch(void* const* d_in, const int* in_sizes, int n_in,
                              void* d_out, int out_size)
{
    const int*   src = (const int*)  d_in[0];
    const float* emb = (const float*)d_in[1];
    const float* Wxh = (const float*)d_in[2];
    const float* bxh = (const float*)d_in[3];
    const float* Whh = (const float*)d_in[4];
    float* out = (float*)d_out;

    static int smem_set = 0;
    const int scan_smem = (32768 + 16384) * sizeof(float);   // 196608 B
    if (!smem_set) {
        cudaFuncSetAttribute(rnn_scan_kernel,
                             cudaFuncAttributeMaxDynamicSharedMemorySize, scan_smem);
        smem_set = 1;
    }

    init_kernel<<<256, 256>>>();
    probe_kernel<<<1, 32>>>();       // ncu alignment: capture lands on the scan
    xproj_kernel<<<dim3(8, SRC_LEN), 256>>>(src, emb, Wxh, bxh);
    rnn_scan_kernel<<<NBLK, 512, scan_smem>>>(Whh, out);
}